// round 1
// baseline (speedup 1.0000x reference)
#include <cuda_runtime.h>

// Accumulators: [0]=sum(diff^2), [1..5]=per-bin sum(diff), [6..10]=per-bin count
__device__ double g_acc[11];

__global__ void zero_acc_kernel() {
    int i = threadIdx.x;
    if (i < 11) g_acc[i] = 0.0;
}

#define PROC(pv, tv)                                                        \
    do {                                                                    \
        float d_ = (pv) - (tv);                                             \
        mse = fmaf(d_, d_, mse);                                            \
        float t_ = (tv);                                                    \
        int idx = -1;                                                       \
        idx += (t_ >= q0); idx += (t_ >= q1); idx += (t_ >= q2);            \
        idx += (t_ >= q3); idx += (t_ >= q4); idx += (t_ >= q5);            \
        if (idx == 5 && t_ == q5) idx = 4;                                  \
        if (idx == 0) { s0 += d_; c0 += 1.0f; }                             \
        if (idx == 1) { s1 += d_; c1 += 1.0f; }                             \
        if (idx == 2) { s2 += d_; c2 += 1.0f; }                             \
        if (idx == 3) { s3 += d_; c3 += 1.0f; }                             \
        if (idx == 4) { s4 += d_; c4 += 1.0f; }                             \
    } while (0)

__global__ void __launch_bounds__(256)
reduce_kernel(const float* __restrict__ y_pred,
              const float* __restrict__ y_true,
              const float* __restrict__ quants,
              int n) {
    const float q0 = __ldg(&quants[0]);
    const float q1 = __ldg(&quants[1]);
    const float q2 = __ldg(&quants[2]);
    const float q3 = __ldg(&quants[3]);
    const float q4 = __ldg(&quants[4]);
    const float q5 = __ldg(&quants[5]);

    float mse = 0.0f;
    float s0 = 0.0f, s1 = 0.0f, s2 = 0.0f, s3 = 0.0f, s4 = 0.0f;
    float c0 = 0.0f, c1 = 0.0f, c2 = 0.0f, c3 = 0.0f, c4 = 0.0f;

    const int tid    = blockIdx.x * blockDim.x + threadIdx.x;
    const int stride = gridDim.x * blockDim.x;
    const int n4     = n >> 2;

    const float4* __restrict__ p4 = (const float4*)y_pred;
    const float4* __restrict__ t4 = (const float4*)y_true;

    for (int i = tid; i < n4; i += stride) {
        float4 p = p4[i];
        float4 t = t4[i];
        PROC(p.x, t.x);
        PROC(p.y, t.y);
        PROC(p.z, t.z);
        PROC(p.w, t.w);
    }
    // scalar tail (n not divisible by 4)
    for (int i = (n4 << 2) + tid; i < n; i += stride) {
        float p = y_pred[i];
        float t = y_true[i];
        PROC(p, t);
    }

    // --- warp-level reduction of 11 partials ---
    float v[11] = {mse, s0, s1, s2, s3, s4, c0, c1, c2, c3, c4};
#pragma unroll
    for (int k = 0; k < 11; k++) {
#pragma unroll
        for (int off = 16; off > 0; off >>= 1)
            v[k] += __shfl_down_sync(0xFFFFFFFFu, v[k], off);
    }

    __shared__ float sh[8][11];  // 256/32 = 8 warps
    const int wid = threadIdx.x >> 5;
    const int lid = threadIdx.x & 31;
    if (lid == 0) {
#pragma unroll
        for (int k = 0; k < 11; k++) sh[wid][k] = v[k];
    }
    __syncthreads();

    // threads 0..10 each sum one column across warps and push to global
    if (threadIdx.x < 11) {
        float acc = 0.0f;
        const int nwarps = blockDim.x >> 5;
#pragma unroll
        for (int w = 0; w < 8; w++)
            if (w < nwarps) acc += sh[w][threadIdx.x];
        atomicAdd(&g_acc[threadIdx.x], (double)acc);
    }
}

__global__ void finalize_kernel(float* __restrict__ out, int n) {
    double mse = g_acc[0] / (double)n;
    double m = 0.0;
#pragma unroll
    for (int j = 0; j < 5; j++) {
        double s = g_acc[1 + j];
        double c = g_acc[6 + j];
        double b = s / fmax(c, 1.0);
        double b2 = (c > 0.0) ? b * b : 0.0;
        m = fmax(m, b2);
    }
    m = fmax(m, 0.0);
    out[0] = (float)(mse + 5.0 * m);
}

extern "C" void kernel_launch(void* const* d_in, const int* in_sizes, int n_in,
                              void* d_out, int out_size) {
    const float* y_pred = (const float*)d_in[0];
    const float* y_true = (const float*)d_in[1];
    const float* quants = (const float*)d_in[2];
    float* out = (float*)d_out;
    const int n = in_sizes[0];

    zero_acc_kernel<<<1, 32>>>();
    reduce_kernel<<<2048, 256>>>(y_pred, y_true, quants, n);
    finalize_kernel<<<1, 1>>>(out, n);
}